// round 1
// baseline (speedup 1.0000x reference)
#include <cuda_runtime.h>
#include <cstdint>
#include <cstddef>

#define NN 100000
#define EE 1600000
#define H 128
#define D 128
#define LN_EPS 1e-5f

// Scratch (static device globals — no allocations allowed)
__device__ float g_h0[(size_t)NN * H];   // GEMM output (residual source)
__device__ float g_act[(size_t)NN * H];  // post-LN/ReLU activations
__device__ float g_agg[(size_t)NN * H];  // layer-0 aggregation
__device__ int   g_is64;                 // edge_index dtype flag

// ---------------------------------------------------------------------------
// Detect whether edge_index is int64 (odd 32-bit words all zero) or int32.
// Node ids < 100000 < 2^31, nonnegative, so int64 ⇒ high words are 0.
// Deterministic, runs every launch.
// ---------------------------------------------------------------------------
__global__ void detect_kernel(const int* __restrict__ w) {
    __shared__ int s;
    if (threadIdx.x == 0) s = 0;
    __syncthreads();
    int acc = 0;
    for (int i = threadIdx.x; i < 2048; i += blockDim.x) acc |= w[2 * i + 1];
    if (acc) atomicOr(&s, 1);
    __syncthreads();
    if (threadIdx.x == 0) g_is64 = (s == 0) ? 1 : 0;
}

// ---------------------------------------------------------------------------
// GEMM: out[m][n] = sum_k X[m][k] * W[n][k] + bias[n]
// BM=128, BN=128 (full), BK=16. W held fully in smem (transposed, padded),
// X streamed in 16-wide chunks. 256 threads, 8x8 micro-tile per thread.
// ---------------------------------------------------------------------------
#define GEMM_SMEM_FLOATS (D * (H + 1) + 16 * (H + 1))

__global__ void __launch_bounds__(256, 1) gemm_kernel(
    const float* __restrict__ X, const float* __restrict__ W,
    const float* __restrict__ bias, float* __restrict__ out) {
    extern __shared__ float sm[];
    float* sWT = sm;               // [k][n], stride 129
    float* sXT = sm + D * (H + 1); // [kk][m], stride 129

    const int tid = threadIdx.x;
    const int m0 = blockIdx.x * 128;

    // Load W [H][D] row-major -> sWT[k*129+n]
    const float4* W4 = (const float4*)W;
    for (int i = tid; i < H * (D / 4); i += 256) {
        int n = i >> 5, kq = i & 31;
        float4 w = W4[i];
        int k = kq * 4;
        sWT[(k + 0) * 129 + n] = w.x;
        sWT[(k + 1) * 129 + n] = w.y;
        sWT[(k + 2) * 129 + n] = w.z;
        sWT[(k + 3) * 129 + n] = w.w;
    }

    const int ty = tid >> 4, tx = tid & 15;
    float acc[8][8];
#pragma unroll
    for (int i = 0; i < 8; i++)
#pragma unroll
        for (int j = 0; j < 8; j++) acc[i][j] = 0.f;

    const float4* X4 = (const float4*)X;
    for (int k0 = 0; k0 < D; k0 += 16) {
        __syncthreads();
        // Load X tile: 128 rows x 16 k -> sXT[kk*129+m]
        for (int i = tid; i < 512; i += 256) {
            int m = i >> 2, kq = i & 3;
            int row = m0 + m;
            float4 x = make_float4(0.f, 0.f, 0.f, 0.f);
            if (row < NN) x = X4[(size_t)row * (D / 4) + (k0 >> 2) + kq];
            int k = kq * 4;
            sXT[(k + 0) * 129 + m] = x.x;
            sXT[(k + 1) * 129 + m] = x.y;
            sXT[(k + 2) * 129 + m] = x.z;
            sXT[(k + 3) * 129 + m] = x.w;
        }
        __syncthreads();
#pragma unroll
        for (int kk = 0; kk < 16; kk++) {
            float a[8], bv[8];
#pragma unroll
            for (int i = 0; i < 8; i++) a[i] = sXT[kk * 129 + ty * 8 + i];
#pragma unroll
            for (int j = 0; j < 8; j++) bv[j] = sWT[(k0 + kk) * 129 + tx * 8 + j];
#pragma unroll
            for (int i = 0; i < 8; i++)
#pragma unroll
                for (int j = 0; j < 8; j++) acc[i][j] += a[i] * bv[j];
        }
    }

#pragma unroll
    for (int i = 0; i < 8; i++) {
        int row = m0 + ty * 8 + i;
        if (row < NN) {
#pragma unroll
            for (int j = 0; j < 8; j++) {
                int col = tx * 8 + j;
                out[(size_t)row * H + col] = acc[i][j] + bias[col];
            }
        }
    }
}

// ---------------------------------------------------------------------------
// LayerNorm (+optional residual) + ReLU. One warp per row (128 cols).
// ---------------------------------------------------------------------------
__global__ void lnrelu_kernel(const float* __restrict__ in,
                              const float* __restrict__ res,
                              const float* __restrict__ scale,
                              const float* __restrict__ bias,
                              float* __restrict__ out) {
    const int warp = threadIdx.x >> 5, lane = threadIdx.x & 31;
    const int row = blockIdx.x * 8 + warp;
    if (row >= NN) return;
    const size_t base = (size_t)row * H + lane * 4;

    float4 v = *(const float4*)(in + base);
    if (res) {
        float4 r = *(const float4*)(res + base);
        v.x += r.x; v.y += r.y; v.z += r.z; v.w += r.w;
    }
    float s  = v.x + v.y + v.z + v.w;
    float sq = v.x * v.x + v.y * v.y + v.z * v.z + v.w * v.w;
#pragma unroll
    for (int o = 16; o > 0; o >>= 1) {
        s  += __shfl_xor_sync(0xFFFFFFFFu, s, o);
        sq += __shfl_xor_sync(0xFFFFFFFFu, sq, o);
    }
    const float mu  = s * (1.f / H);
    const float var = sq * (1.f / H) - mu * mu;
    const float rs  = rsqrtf(var + LN_EPS);
    float4 sc = *(const float4*)(scale + lane * 4);
    float4 bi = *(const float4*)(bias + lane * 4);
    float4 y;
    y.x = fmaxf((v.x - mu) * rs * sc.x + bi.x, 0.f);
    y.y = fmaxf((v.y - mu) * rs * sc.y + bi.y, 0.f);
    y.z = fmaxf((v.z - mu) * rs * sc.z + bi.z, 0.f);
    y.w = fmaxf((v.w - mu) * rs * sc.w + bi.w, 0.f);
    *(float4*)(out + base) = y;
}

// ---------------------------------------------------------------------------
// SpMM scatter: out[dst] += h[src] * e_feat.  One warp per edge,
// lane handles 4 columns via one vectorized red.global.add.v4.f32.
// ---------------------------------------------------------------------------
__global__ void __launch_bounds__(256) spmm_kernel(
    const float* __restrict__ h, const void* __restrict__ ei,
    const float* __restrict__ ef, float* __restrict__ out) {
    const int t = blockIdx.x * blockDim.x + threadIdx.x;
    const int e = t >> 5;
    const int lane = t & 31;
    if (e >= EE) return;

    long long src, dst;
    if (g_is64) {
        const long long* p = (const long long*)ei;
        src = p[e];
        dst = p[EE + e];
    } else {
        const int* p = (const int*)ei;
        src = p[e];
        dst = p[EE + e];
    }
    const float w = ef[e];
    float4 v = *(const float4*)(h + (size_t)src * H + lane * 4);
    float* o = out + (size_t)dst * H + lane * 4;
    asm volatile("red.global.add.v4.f32 [%0], {%1, %2, %3, %4};"
                 :: "l"(o), "f"(v.x * w), "f"(v.y * w), "f"(v.z * w), "f"(v.w * w)
                 : "memory");
}

// ---------------------------------------------------------------------------
// Launch
// ---------------------------------------------------------------------------
extern "C" void kernel_launch(void* const* d_in, const int* in_sizes, int n_in,
                              void* d_out, int out_size) {
    const float* x  = (const float*)d_in[0];
    const void*  ei = d_in[1];
    const float* ef = (const float*)d_in[2];
    const float* w  = (const float*)d_in[3];
    const float* b  = (const float*)d_in[4];
    const float* ls = (const float*)d_in[5];
    const float* lb = (const float*)d_in[6];
    float* out = (float*)d_out;

    float *h0, *act, *agg;
    cudaGetSymbolAddress((void**)&h0,  g_h0);
    cudaGetSymbolAddress((void**)&act, g_act);
    cudaGetSymbolAddress((void**)&agg, g_agg);

    const int smem = GEMM_SMEM_FLOATS * (int)sizeof(float);
    cudaFuncSetAttribute(gemm_kernel, cudaFuncAttributeMaxDynamicSharedMemorySize, smem);

    detect_kernel<<<1, 256>>>((const int*)ei);
    gemm_kernel<<<(NN + 127) / 128, 256, smem>>>(x, w, b, h0);

    // Layer 0: LN -> ReLU -> SpMM
    lnrelu_kernel<<<(NN + 7) / 8, 256>>>(h0, nullptr, ls, lb, act);
    cudaMemsetAsync(agg, 0, (size_t)NN * H * sizeof(float));
    spmm_kernel<<<(EE * 32 + 255) / 256, 256>>>(act, ei, ef, agg);

    // Layer 1: residual -> LN -> ReLU -> SpMM (into d_out)
    lnrelu_kernel<<<(NN + 7) / 8, 256>>>(agg, h0, ls + H, lb + H, act);
    cudaMemsetAsync(out, 0, (size_t)NN * H * sizeof(float));
    spmm_kernel<<<(EE * 32 + 255) / 256, 256>>>(act, ei, ef, out);
}

// round 6
// speedup vs baseline: 1.3181x; 1.3181x over previous
#include <cuda_runtime.h>
#include <cstdint>
#include <cstddef>

#define NN 100000
#define EE 1600000
#define H 128
#define D 128
#define LN_EPS 1e-5f

// Scratch (static device globals — no allocations allowed)
__device__ float g_h0[(size_t)NN * H];    // GEMM output (residual source)
__device__ float g_act[(size_t)NN * H];   // post-LN/ReLU activations (layer-0 input)
__device__ float g_agg[(size_t)NN * H];   // layer-0 gather output (layer-1 input)
__device__ int   g_cnt[NN];               // per-dst degree
__device__ int   g_rowptr[NN + 1];        // CSR row pointers
__device__ int   g_cursor[NN];            // scatter cursors
__device__ int   g_esrc[EE];              // CSR: src node per slot
__device__ float g_ew[EE];                // CSR: edge weight per slot
__device__ int   g_is64;                  // edge_index dtype flag

// ---------------------------------------------------------------------------
// Detect int64 vs int32 edge_index (ids < 2^31 so int64 => high words zero).
// ---------------------------------------------------------------------------
__global__ void detect_kernel(const int* __restrict__ w) {
    __shared__ int s;
    if (threadIdx.x == 0) s = 0;
    __syncthreads();
    int acc = 0;
    for (int i = threadIdx.x; i < 2048; i += blockDim.x) acc |= w[2 * i + 1];
    if (acc) atomicOr(&s, 1);
    __syncthreads();
    if (threadIdx.x == 0) g_is64 = (s == 0) ? 1 : 0;
}

__device__ __forceinline__ void load_edge(const void* ei, int e, int& src, int& dst) {
    if (g_is64) {
        const long long* p = (const long long*)ei;
        src = (int)p[e];
        dst = (int)p[EE + e];
    } else {
        const int* p = (const int*)ei;
        src = p[e];
        dst = p[EE + e];
    }
}

// ---------------------------------------------------------------------------
// CSR build: histogram -> scan -> scatter
// ---------------------------------------------------------------------------
__global__ void __launch_bounds__(256) hist_kernel(const void* __restrict__ ei) {
    int e = blockIdx.x * 256 + threadIdx.x;
    if (e >= EE) return;
    int src, dst;
    load_edge(ei, e, src, dst);
    atomicAdd(&g_cnt[dst], 1);
}

__global__ void __launch_bounds__(1024) scan_kernel() {
    __shared__ int part[1024];
    const int t = threadIdx.x;
    const int per = (NN + 1023) / 1024;  // 98
    const int b = t * per;
    int s = 0;
    for (int i = 0; i < per; i++) {
        int idx = b + i;
        if (idx < NN) s += g_cnt[idx];
    }
    part[t] = s;
    __syncthreads();
    for (int o = 1; o < 1024; o <<= 1) {
        int v = (t >= o) ? part[t - o] : 0;
        __syncthreads();
        part[t] += v;
        __syncthreads();
    }
    int run = part[t] - s;  // exclusive prefix of this chunk
    for (int i = 0; i < per; i++) {
        int idx = b + i;
        if (idx < NN) {
            g_rowptr[idx] = run;
            g_cursor[idx] = run;
            run += g_cnt[idx];
        }
    }
    if (t == 1023) g_rowptr[NN] = EE;
}

__global__ void __launch_bounds__(256) scatter_kernel(const void* __restrict__ ei,
                                                      const float* __restrict__ ef) {
    int e = blockIdx.x * 256 + threadIdx.x;
    if (e >= EE) return;
    int src, dst;
    load_edge(ei, e, src, dst);
    int pos = atomicAdd(&g_cursor[dst], 1);
    g_esrc[pos] = src;
    g_ew[pos] = ef[e];
}

// ---------------------------------------------------------------------------
// GEMM: out[m][n] = sum_k X[m][k] * W[n][k] + bias[n]
// ---------------------------------------------------------------------------
#define GEMM_SMEM_FLOATS (D * (H + 1) + 16 * (H + 1))

__global__ void __launch_bounds__(256, 1) gemm_kernel(
    const float* __restrict__ X, const float* __restrict__ W,
    const float* __restrict__ bias, float* __restrict__ out) {
    extern __shared__ float sm[];
    float* sWT = sm;               // [k][n], stride 129
    float* sXT = sm + D * (H + 1); // [kk][m], stride 129

    const int tid = threadIdx.x;
    const int m0 = blockIdx.x * 128;

    const float4* W4 = (const float4*)W;
    for (int i = tid; i < H * (D / 4); i += 256) {
        int n = i >> 5, kq = i & 31;
        float4 w = W4[i];
        int k = kq * 4;
        sWT[(k + 0) * 129 + n] = w.x;
        sWT[(k + 1) * 129 + n] = w.y;
        sWT[(k + 2) * 129 + n] = w.z;
        sWT[(k + 3) * 129 + n] = w.w;
    }

    const int ty = tid >> 4, tx = tid & 15;
    float acc[8][8];
#pragma unroll
    for (int i = 0; i < 8; i++)
#pragma unroll
        for (int j = 0; j < 8; j++) acc[i][j] = 0.f;

    const float4* X4 = (const float4*)X;
    for (int k0 = 0; k0 < D; k0 += 16) {
        __syncthreads();
        for (int i = tid; i < 512; i += 256) {
            int m = i >> 2, kq = i & 3;
            int row = m0 + m;
            float4 x = make_float4(0.f, 0.f, 0.f, 0.f);
            if (row < NN) x = X4[(size_t)row * (D / 4) + (k0 >> 2) + kq];
            int k = kq * 4;
            sXT[(k + 0) * 129 + m] = x.x;
            sXT[(k + 1) * 129 + m] = x.y;
            sXT[(k + 2) * 129 + m] = x.z;
            sXT[(k + 3) * 129 + m] = x.w;
        }
        __syncthreads();
#pragma unroll
        for (int kk = 0; kk < 16; kk++) {
            float a[8], bv[8];
#pragma unroll
            for (int i = 0; i < 8; i++) a[i] = sXT[kk * 129 + ty * 8 + i];
#pragma unroll
            for (int j = 0; j < 8; j++) bv[j] = sWT[(k0 + kk) * 129 + tx * 8 + j];
#pragma unroll
            for (int i = 0; i < 8; i++)
#pragma unroll
                for (int j = 0; j < 8; j++) acc[i][j] += a[i] * bv[j];
        }
    }

#pragma unroll
    for (int i = 0; i < 8; i++) {
        int row = m0 + ty * 8 + i;
        if (row < NN) {
#pragma unroll
            for (int j = 0; j < 8; j++) {
                int col = tx * 8 + j;
                out[(size_t)row * H + col] = acc[i][j] + bias[col];
            }
        }
    }
}

// ---------------------------------------------------------------------------
// LayerNorm + ReLU (layer 0, no residual). One warp per row.
// ---------------------------------------------------------------------------
__global__ void lnrelu_kernel(const float* __restrict__ in,
                              const float* __restrict__ scale,
                              const float* __restrict__ bias,
                              float* __restrict__ out) {
    const int warp = threadIdx.x >> 5, lane = threadIdx.x & 31;
    const int row = blockIdx.x * 8 + warp;
    if (row >= NN) return;
    const size_t base = (size_t)row * H + lane * 4;

    float4 v = *(const float4*)(in + base);
    float s  = v.x + v.y + v.z + v.w;
    float sq = v.x * v.x + v.y * v.y + v.z * v.z + v.w * v.w;
#pragma unroll
    for (int o = 16; o > 0; o >>= 1) {
        s  += __shfl_xor_sync(0xFFFFFFFFu, s, o);
        sq += __shfl_xor_sync(0xFFFFFFFFu, sq, o);
    }
    const float mu  = s * (1.f / H);
    const float var = sq * (1.f / H) - mu * mu;
    const float rs  = rsqrtf(var + LN_EPS);
    float4 sc = *(const float4*)(scale + lane * 4);
    float4 bi = *(const float4*)(bias + lane * 4);
    float4 y;
    y.x = fmaxf((v.x - mu) * rs * sc.x + bi.x, 0.f);
    y.y = fmaxf((v.y - mu) * rs * sc.y + bi.y, 0.f);
    y.z = fmaxf((v.z - mu) * rs * sc.z + bi.z, 0.f);
    y.w = fmaxf((v.w - mu) * rs * sc.w + bi.w, 0.f);
    *(float4*)(out + base) = y;
}

// ---------------------------------------------------------------------------
// CSR gather SpMM: one warp per dst row; register accumulation; no atomics.
// Inner loop unrolled x4 for MLP. Optional fused epilogue: residual+LN+ReLU.
// NOTE: in and out must be DISTINCT buffers (reads arbitrary rows of `h`).
// ---------------------------------------------------------------------------
__global__ void __launch_bounds__(256) gather_kernel(
    const float* __restrict__ h, const float* __restrict__ res,
    const float* __restrict__ scale, const float* __restrict__ bias,
    float* __restrict__ out) {
    const int warp = (blockIdx.x * 256 + threadIdx.x) >> 5;
    const int lane = threadIdx.x & 31;
    if (warp >= NN) return;

    int j = g_rowptr[warp];
    const int e = g_rowptr[warp + 1];
    float4 acc = make_float4(0.f, 0.f, 0.f, 0.f);
    const int col = lane * 4;

    for (; j + 4 <= e; j += 4) {
        int s0 = g_esrc[j], s1 = g_esrc[j + 1], s2 = g_esrc[j + 2], s3 = g_esrc[j + 3];
        float w0 = g_ew[j], w1 = g_ew[j + 1], w2 = g_ew[j + 2], w3 = g_ew[j + 3];
        float4 v0 = *(const float4*)(h + (size_t)s0 * H + col);
        float4 v1 = *(const float4*)(h + (size_t)s1 * H + col);
        float4 v2 = *(const float4*)(h + (size_t)s2 * H + col);
        float4 v3 = *(const float4*)(h + (size_t)s3 * H + col);
        acc.x += v0.x * w0 + v1.x * w1 + v2.x * w2 + v3.x * w3;
        acc.y += v0.y * w0 + v1.y * w1 + v2.y * w2 + v3.y * w3;
        acc.z += v0.z * w0 + v1.z * w1 + v2.z * w2 + v3.z * w3;
        acc.w += v0.w * w0 + v1.w * w1 + v2.w * w2 + v3.w * w3;
    }
    for (; j < e; j++) {
        int sA = g_esrc[j];
        float wA = g_ew[j];
        float4 vA = *(const float4*)(h + (size_t)sA * H + col);
        acc.x += vA.x * wA;
        acc.y += vA.y * wA;
        acc.z += vA.z * wA;
        acc.w += vA.w * wA;
    }

    const size_t base = (size_t)warp * H + col;
    if (res) {
        float4 r = *(const float4*)(res + base);
        acc.x += r.x; acc.y += r.y; acc.z += r.z; acc.w += r.w;
        float s  = acc.x + acc.y + acc.z + acc.w;
        float sq = acc.x * acc.x + acc.y * acc.y + acc.z * acc.z + acc.w * acc.w;
#pragma unroll
        for (int o = 16; o > 0; o >>= 1) {
            s  += __shfl_xor_sync(0xFFFFFFFFu, s, o);
            sq += __shfl_xor_sync(0xFFFFFFFFu, sq, o);
        }
        const float mu  = s * (1.f / H);
        const float var = sq * (1.f / H) - mu * mu;
        const float rs  = rsqrtf(var + LN_EPS);
        float4 sc = *(const float4*)(scale + col);
        float4 bi = *(const float4*)(bias + col);
        acc.x = fmaxf((acc.x - mu) * rs * sc.x + bi.x, 0.f);
        acc.y = fmaxf((acc.y - mu) * rs * sc.y + bi.y, 0.f);
        acc.z = fmaxf((acc.z - mu) * rs * sc.z + bi.z, 0.f);
        acc.w = fmaxf((acc.w - mu) * rs * sc.w + bi.w, 0.f);
    }
    *(float4*)(out + base) = acc;
}

// ---------------------------------------------------------------------------
// Launch
// ---------------------------------------------------------------------------
extern "C" void kernel_launch(void* const* d_in, const int* in_sizes, int n_in,
                              void* d_out, int out_size) {
    const float* x  = (const float*)d_in[0];
    const void*  ei = d_in[1];
    const float* ef = (const float*)d_in[2];
    const float* w  = (const float*)d_in[3];
    const float* b  = (const float*)d_in[4];
    const float* ls = (const float*)d_in[5];
    const float* lb = (const float*)d_in[6];
    float* out = (float*)d_out;

    float *h0, *act, *agg;
    int* cnt;
    cudaGetSymbolAddress((void**)&h0,  g_h0);
    cudaGetSymbolAddress((void**)&act, g_act);
    cudaGetSymbolAddress((void**)&agg, g_agg);
    cudaGetSymbolAddress((void**)&cnt, g_cnt);

    const int smem = GEMM_SMEM_FLOATS * (int)sizeof(float);
    cudaFuncSetAttribute(gemm_kernel, cudaFuncAttributeMaxDynamicSharedMemorySize, smem);

    detect_kernel<<<1, 256>>>((const int*)ei);

    // CSR build (shared by both SpMM passes)
    cudaMemsetAsync(cnt, 0, NN * sizeof(int));
    hist_kernel<<<(EE + 255) / 256, 256>>>(ei);
    scan_kernel<<<1, 1024>>>();
    scatter_kernel<<<(EE + 255) / 256, 256>>>(ei, ef);

    // Dense path
    gemm_kernel<<<(NN + 127) / 128, 256, smem>>>(x, w, b, h0);
    lnrelu_kernel<<<(NN + 7) / 8, 256>>>(h0, ls, lb, act);

    // Layer 0 gather (act -> agg), fused residual+LN+ReLU epilogue for layer 1
    gather_kernel<<<(NN * 32 + 255) / 256, 256>>>(act, h0, ls + H, lb + H, agg);
    // Layer 1 gather (agg -> out)
    gather_kernel<<<(NN * 32 + 255) / 256, 256>>>(agg, nullptr, nullptr, nullptr, out);
}

// round 7
// speedup vs baseline: 1.3240x; 1.0045x over previous
#include <cuda_runtime.h>
#include <cstdint>
#include <cstddef>

#define NN 100000
#define EE 1600000
#define H 128
#define D 128
#define LN_EPS 1e-5f

// Scratch (static device globals — no allocations allowed)
__device__ float g_h0[(size_t)NN * H];    // GEMM output (residual source)
__device__ float g_act[(size_t)NN * H];   // post-LN/ReLU activations (layer-0 input)
__device__ float g_agg[(size_t)NN * H];   // layer-0 gather output (layer-1 input)
__device__ int   g_cnt[NN];               // per-dst degree
__device__ int   g_rowptr[NN + 1];        // CSR row pointers
__device__ int   g_cursor[NN];            // scatter cursors
__device__ int2  g_edge[EE];              // CSR: packed (src, weight-as-int)
__device__ int   g_is64;                  // edge_index dtype flag

// ---------------------------------------------------------------------------
// Detect int64 vs int32 edge_index (ids < 2^31 so int64 => high words zero).
// ---------------------------------------------------------------------------
__global__ void detect_kernel(const int* __restrict__ w) {
    __shared__ int s;
    if (threadIdx.x == 0) s = 0;
    __syncthreads();
    int acc = 0;
    for (int i = threadIdx.x; i < 2048; i += blockDim.x) acc |= w[2 * i + 1];
    if (acc) atomicOr(&s, 1);
    __syncthreads();
    if (threadIdx.x == 0) g_is64 = (s == 0) ? 1 : 0;
}

__device__ __forceinline__ void load_edge(const void* ei, int e, int& src, int& dst) {
    if (g_is64) {
        const long long* p = (const long long*)ei;
        src = (int)p[e];
        dst = (int)p[EE + e];
    } else {
        const int* p = (const int*)ei;
        src = p[e];
        dst = p[EE + e];
    }
}

// ---------------------------------------------------------------------------
// CSR build: histogram -> scan -> scatter
// ---------------------------------------------------------------------------
__global__ void __launch_bounds__(256) hist_kernel(const void* __restrict__ ei) {
    int e = blockIdx.x * 256 + threadIdx.x;
    if (e >= EE) return;
    int src, dst;
    load_edge(ei, e, src, dst);
    atomicAdd(&g_cnt[dst], 1);
}

__global__ void __launch_bounds__(1024) scan_kernel() {
    __shared__ int part[1024];
    const int t = threadIdx.x;
    const int per = (NN + 1023) / 1024;  // 98
    const int b = t * per;
    int s = 0;
    for (int i = 0; i < per; i++) {
        int idx = b + i;
        if (idx < NN) s += g_cnt[idx];
    }
    part[t] = s;
    __syncthreads();
    for (int o = 1; o < 1024; o <<= 1) {
        int v = (t >= o) ? part[t - o] : 0;
        __syncthreads();
        part[t] += v;
        __syncthreads();
    }
    int run = part[t] - s;  // exclusive prefix of this chunk
    for (int i = 0; i < per; i++) {
        int idx = b + i;
        if (idx < NN) {
            g_rowptr[idx] = run;
            g_cursor[idx] = run;
            run += g_cnt[idx];
        }
    }
    if (t == 1023) g_rowptr[NN] = EE;
}

__global__ void __launch_bounds__(256) scatter_kernel(const void* __restrict__ ei,
                                                      const float* __restrict__ ef) {
    int e = blockIdx.x * 256 + threadIdx.x;
    if (e >= EE) return;
    int src, dst;
    load_edge(ei, e, src, dst);
    int pos = atomicAdd(&g_cursor[dst], 1);
    g_edge[pos] = make_int2(src, __float_as_int(ef[e]));
}

// ---------------------------------------------------------------------------
// GEMM: h = X @ W^T + bias, fused epilogue writes BOTH:
//   h0  = h                      (residual source)
//   act = relu(layernorm(h))     (layer-0 input)
// LN reduction: each row's 128 cols live in 16 tx-lanes of one half-warp.
// ---------------------------------------------------------------------------
#define GEMM_SMEM_FLOATS (D * (H + 1) + 16 * (H + 1))

__global__ void __launch_bounds__(256, 1) gemm_kernel(
    const float* __restrict__ X, const float* __restrict__ W,
    const float* __restrict__ bias,
    const float* __restrict__ ln_s, const float* __restrict__ ln_b,
    float* __restrict__ h0, float* __restrict__ act) {
    extern __shared__ float sm[];
    float* sWT = sm;               // [k][n], stride 129
    float* sXT = sm + D * (H + 1); // [kk][m], stride 129

    const int tid = threadIdx.x;
    const int m0 = blockIdx.x * 128;

    const float4* W4 = (const float4*)W;
    for (int i = tid; i < H * (D / 4); i += 256) {
        int n = i >> 5, kq = i & 31;
        float4 w = W4[i];
        int k = kq * 4;
        sWT[(k + 0) * 129 + n] = w.x;
        sWT[(k + 1) * 129 + n] = w.y;
        sWT[(k + 2) * 129 + n] = w.z;
        sWT[(k + 3) * 129 + n] = w.w;
    }

    const int ty = tid >> 4, tx = tid & 15;
    float acc[8][8];
#pragma unroll
    for (int i = 0; i < 8; i++)
#pragma unroll
        for (int j = 0; j < 8; j++) acc[i][j] = 0.f;

    const float4* X4 = (const float4*)X;
    for (int k0 = 0; k0 < D; k0 += 16) {
        __syncthreads();
        for (int i = tid; i < 512; i += 256) {
            int m = i >> 2, kq = i & 3;
            int row = m0 + m;
            float4 x = make_float4(0.f, 0.f, 0.f, 0.f);
            if (row < NN) x = X4[(size_t)row * (D / 4) + (k0 >> 2) + kq];
            int k = kq * 4;
            sXT[(k + 0) * 129 + m] = x.x;
            sXT[(k + 1) * 129 + m] = x.y;
            sXT[(k + 2) * 129 + m] = x.z;
            sXT[(k + 3) * 129 + m] = x.w;
        }
        __syncthreads();
#pragma unroll
        for (int kk = 0; kk < 16; kk++) {
            float a[8], bv[8];
#pragma unroll
            for (int i = 0; i < 8; i++) a[i] = sXT[kk * 129 + ty * 8 + i];
#pragma unroll
            for (int j = 0; j < 8; j++) bv[j] = sWT[(k0 + kk) * 129 + tx * 8 + j];
#pragma unroll
            for (int i = 0; i < 8; i++)
#pragma unroll
                for (int j = 0; j < 8; j++) acc[i][j] += a[i] * bv[j];
        }
    }

    // Epilogue: bias add + write h0 + LN + ReLU + write act.
    const int colb = tx * 8;
    float bv[8], sc[8], sb[8];
#pragma unroll
    for (int j = 0; j < 8; j++) {
        bv[j] = bias[colb + j];
        sc[j] = ln_s[colb + j];
        sb[j] = ln_b[colb + j];
    }
#pragma unroll
    for (int i = 0; i < 8; i++) {
        const int row = m0 + ty * 8 + i;
        float v[8];
        float s = 0.f, sq = 0.f;
#pragma unroll
        for (int j = 0; j < 8; j++) {
            v[j] = acc[i][j] + bv[j];
            s += v[j];
            sq += v[j] * v[j];
        }
        // reduce across the 16 tx lanes (same ty => same half-warp)
#pragma unroll
        for (int o = 8; o > 0; o >>= 1) {
            s  += __shfl_xor_sync(0xFFFFFFFFu, s, o);
            sq += __shfl_xor_sync(0xFFFFFFFFu, sq, o);
        }
        const float mu  = s * (1.f / H);
        const float var = sq * (1.f / H) - mu * mu;
        const float rs  = rsqrtf(var + LN_EPS);
        if (row < NN) {
            float a[8];
#pragma unroll
            for (int j = 0; j < 8; j++)
                a[j] = fmaxf((v[j] - mu) * rs * sc[j] + sb[j], 0.f);
            float* ph = h0  + (size_t)row * H + colb;
            float* pa = act + (size_t)row * H + colb;
            *(float4*)(ph + 0) = make_float4(v[0], v[1], v[2], v[3]);
            *(float4*)(ph + 4) = make_float4(v[4], v[5], v[6], v[7]);
            *(float4*)(pa + 0) = make_float4(a[0], a[1], a[2], a[3]);
            *(float4*)(pa + 4) = make_float4(a[4], a[5], a[6], a[7]);
        }
    }
}

// ---------------------------------------------------------------------------
// CSR gather SpMM: one warp per dst row; register accumulation; no atomics.
// Packed int2 edges; 8 loads in flight. Optional fused residual+LN+ReLU.
// NOTE: in and out must be DISTINCT buffers (reads arbitrary rows of `h`).
// ---------------------------------------------------------------------------
__global__ void __launch_bounds__(256) gather_kernel(
    const float* __restrict__ h, const float* __restrict__ res,
    const float* __restrict__ scale, const float* __restrict__ bias,
    float* __restrict__ out) {
    const int warp = (blockIdx.x * 256 + threadIdx.x) >> 5;
    const int lane = threadIdx.x & 31;
    if (warp >= NN) return;

    int j = g_rowptr[warp];
    const int e = g_rowptr[warp + 1];
    float4 acc = make_float4(0.f, 0.f, 0.f, 0.f);
    const int col = lane * 4;

    for (; j + 8 <= e; j += 8) {
        int2 ed[8];
#pragma unroll
        for (int q = 0; q < 8; q++) ed[q] = g_edge[j + q];
        float4 v[8];
#pragma unroll
        for (int q = 0; q < 8; q++)
            v[q] = *(const float4*)(h + (size_t)ed[q].x * H + col);
#pragma unroll
        for (int q = 0; q < 8; q++) {
            const float wq = __int_as_float(ed[q].y);
            acc.x += v[q].x * wq;
            acc.y += v[q].y * wq;
            acc.z += v[q].z * wq;
            acc.w += v[q].w * wq;
        }
    }
    for (; j + 2 <= e; j += 2) {
        int2 e0 = g_edge[j], e1 = g_edge[j + 1];
        float4 v0 = *(const float4*)(h + (size_t)e0.x * H + col);
        float4 v1 = *(const float4*)(h + (size_t)e1.x * H + col);
        const float w0 = __int_as_float(e0.y), w1 = __int_as_float(e1.y);
        acc.x += v0.x * w0 + v1.x * w1;
        acc.y += v0.y * w0 + v1.y * w1;
        acc.z += v0.z * w0 + v1.z * w1;
        acc.w += v0.w * w0 + v1.w * w1;
    }
    if (j < e) {
        int2 e0 = g_edge[j];
        float4 v0 = *(const float4*)(h + (size_t)e0.x * H + col);
        const float w0 = __int_as_float(e0.y);
        acc.x += v0.x * w0;
        acc.y += v0.y * w0;
        acc.z += v0.z * w0;
        acc.w += v0.w * w0;
    }

    const size_t base = (size_t)warp * H + col;
    if (res) {
        float4 r = *(const float4*)(res + base);
        acc.x += r.x; acc.y += r.y; acc.z += r.z; acc.w += r.w;
        float s  = acc.x + acc.y + acc.z + acc.w;
        float sq = acc.x * acc.x + acc.y * acc.y + acc.z * acc.z + acc.w * acc.w;
#pragma unroll
        for (int o = 16; o > 0; o >>= 1) {
            s  += __shfl_xor_sync(0xFFFFFFFFu, s, o);
            sq += __shfl_xor_sync(0xFFFFFFFFu, sq, o);
        }
        const float mu  = s * (1.f / H);
        const float var = sq * (1.f / H) - mu * mu;
        const float rs  = rsqrtf(var + LN_EPS);
        float4 sc = *(const float4*)(scale + col);
        float4 bi = *(const float4*)(bias + col);
        acc.x = fmaxf((acc.x - mu) * rs * sc.x + bi.x, 0.f);
        acc.y = fmaxf((acc.y - mu) * rs * sc.y + bi.y, 0.f);
        acc.z = fmaxf((acc.z - mu) * rs * sc.z + bi.z, 0.f);
        acc.w = fmaxf((acc.w - mu) * rs * sc.w + bi.w, 0.f);
    }
    *(float4*)(out + base) = acc;
}

// ---------------------------------------------------------------------------
// Launch
// ---------------------------------------------------------------------------
extern "C" void kernel_launch(void* const* d_in, const int* in_sizes, int n_in,
                              void* d_out, int out_size) {
    const float* x  = (const float*)d_in[0];
    const void*  ei = d_in[1];
    const float* ef = (const float*)d_in[2];
    const float* w  = (const float*)d_in[3];
    const float* b  = (const float*)d_in[4];
    const float* ls = (const float*)d_in[5];
    const float* lb = (const float*)d_in[6];
    float* out = (float*)d_out;

    float *h0, *act, *agg;
    int* cnt;
    cudaGetSymbolAddress((void**)&h0,  g_h0);
    cudaGetSymbolAddress((void**)&act, g_act);
    cudaGetSymbolAddress((void**)&agg, g_agg);
    cudaGetSymbolAddress((void**)&cnt, g_cnt);

    const int smem = GEMM_SMEM_FLOATS * (int)sizeof(float);
    cudaFuncSetAttribute(gemm_kernel, cudaFuncAttributeMaxDynamicSharedMemorySize, smem);

    detect_kernel<<<1, 256>>>((const int*)ei);

    // CSR build (shared by both SpMM passes)
    cudaMemsetAsync(cnt, 0, NN * sizeof(int));
    hist_kernel<<<(EE + 255) / 256, 256>>>(ei);
    scan_kernel<<<1, 1024>>>();
    scatter_kernel<<<(EE + 255) / 256, 256>>>(ei, ef);

    // Dense path: GEMM with fused bias + LN0 + ReLU epilogue
    gemm_kernel<<<(NN + 127) / 128, 256, smem>>>(x, w, b, ls, lb, h0, act);

    // Layer 0 gather (act -> agg), fused residual+LN1+ReLU epilogue
    gather_kernel<<<(NN * 32 + 255) / 256, 256>>>(act, h0, ls + H, lb + H, agg);
    // Layer 1 gather (agg -> out)
    gather_kernel<<<(NN * 32 + 255) / 256, 256>>>(agg, nullptr, nullptr, nullptr, out);
}